// round 15
// baseline (speedup 1.0000x reference)
#include <cuda_runtime.h>
#include <cuda_fp16.h>
#include <math.h>
#include <stdint.h>

#define T_TOK 4096
#define HDIM  1024
#define IDIM  1408
#define NEXP  8
#define NPAIR (T_TOK * 2)
#define N2I   (2 * IDIM)           // 2816 (interleaved gate/up rows)
#define BM 128
#define BN 128
#define BKH 64                     // K halves per stage (128B rows)
#define MAXT 72
#define NT1C (N2I / BN)            // 22 G1 column tiles
#define NT2C (HDIM / BN)           // 8  G2 column tiles
#define PERSIST_CTAS 304           // 2/SM x 152 SMs (GB300); safe if fewer SMs

// smem: rows 128B data + 16B pad = 144B (ldmatrix stride 36 words -> conflict-free)
#define ROWB 144
#define REG  (128 * ROWB)          // 18432 B per operand region
#define STAGEB (2 * REG)           // A + B = 36864
#define SMEM_TOTAL (3 * STAGEB)    // 110592 (triple-buffered) -> 2 CTAs/SM

// ---------------- scratch (static device globals; no allocations) ----------
__device__ int   g_count[NEXP];
__device__ int   g_list [NEXP * T_TOK];
__device__ float g_wt   [NEXP * T_TOK];
__device__ int   g_base [NEXP];
__device__ int   g_tileE[MAXT];
__device__ int   g_tileRow[MAXT];
__device__ int   g_numTiles;
__device__ int   g_ticket;
__device__ int   g_done[MAXT];

__device__ __half g_xh [(size_t)NPAIR * HDIM];
__device__ __half g_w1h[(size_t)NEXP * N2I * HDIM];   // interleaved: row 2i=gate_i, 2i+1=up_i
__device__ __half g_wdh[(size_t)NEXP * HDIM * IDIM];
__device__ __half g_hh [(size_t)NPAIR * IDIM];

// ---------------- helpers -------------------------------------------------
__device__ __forceinline__ uint32_t smem_u32(const void* p) {
    uint32_t a;
    asm("{ .reg .u64 t; cvta.to.shared.u64 t, %1; cvt.u32.u64 %0, t; }" : "=r"(a) : "l"(p));
    return a;
}
__device__ __forceinline__ void cp16(uint32_t s, const void* g, bool v) {
    int sz = v ? 16 : 0;
    asm volatile("cp.async.cg.shared.global [%0], [%1], 16, %2;" :: "r"(s), "l"(g), "r"(sz) : "memory");
}
__device__ __forceinline__ void ldsm4(uint32_t* r, uint32_t addr) {
    asm volatile("ldmatrix.sync.aligned.m8n8.x4.shared.b16 {%0,%1,%2,%3}, [%4];"
                 : "=r"(r[0]), "=r"(r[1]), "=r"(r[2]), "=r"(r[3]) : "r"(addr));
}
__device__ __forceinline__ void mma16816(float* c, const uint32_t* a, uint32_t b0, uint32_t b1) {
    asm volatile("mma.sync.aligned.m16n8k16.row.col.f32.f16.f16.f32 "
                 "{%0,%1,%2,%3}, {%4,%5,%6,%7}, {%8,%9}, {%0,%1,%2,%3};"
                 : "+f"(c[0]), "+f"(c[1]), "+f"(c[2]), "+f"(c[3])
                 : "r"(a[0]), "r"(a[1]), "r"(a[2]), "r"(a[3]), "r"(b0), "r"(b1));
}
__device__ __forceinline__ void h_store4(float4 v, __half* hp) {
    ((__half2*)hp)[0] = __halves2half2(__float2half_rn(v.x), __float2half_rn(v.y));
    ((__half2*)hp)[1] = __halves2half2(__float2half_rn(v.z), __float2half_rn(v.w));
}

// ---------------- zero output + control state -----------------------------
__global__ void k_zero(float* __restrict__ out) {
    size_t idx = (size_t)blockIdx.x * blockDim.x + threadIdx.x;
    if (idx < (size_t)T_TOK * HDIM / 4)
        *(float4*)(out + idx * 4) = make_float4(0.f, 0.f, 0.f, 0.f);
    if (blockIdx.x == 0) {
        if (threadIdx.x < NEXP) g_count[threadIdx.x] = 0;
        if (threadIdx.x < MAXT) g_done[threadIdx.x] = 0;
        if (threadIdx.x == 128) g_ticket = 0;
    }
}

// ---------------- router: one warp per token ------------------------------
__global__ void k_router(const float* __restrict__ x, const float* __restrict__ rw) {
    int warp = (blockIdx.x * blockDim.x + threadIdx.x) >> 5;
    int lane = threadIdx.x & 31;
    if (warp >= T_TOK) return;
    const float* xr = x + (size_t)warp * HDIM;

    float xv[32];
#pragma unroll
    for (int j = 0; j < 32; j++) xv[j] = xr[lane + j * 32];

    float logits[NEXP];
#pragma unroll
    for (int e = 0; e < NEXP; e++) {
        const float* wr = rw + (size_t)e * HDIM;
        float acc = 0.f;
#pragma unroll
        for (int j = 0; j < 32; j++) acc += xv[j] * wr[lane + j * 32];
#pragma unroll
        for (int s = 16; s > 0; s >>= 1) acc += __shfl_xor_sync(0xffffffffu, acc, s);
        logits[e] = acc;
    }

    if (lane == 0) {
        int e1 = 0;
#pragma unroll
        for (int e = 1; e < NEXP; e++) if (logits[e] > logits[e1]) e1 = e;
        int e2 = (e1 == 0) ? 1 : 0;
#pragma unroll
        for (int e = 0; e < NEXP; e++)
            if (e != e1 && logits[e] > logits[e2]) e2 = e;
        float t  = expf(logits[e2] - logits[e1]);
        float w1 = 1.f / (1.f + t);
        float w2 = t   / (1.f + t);

        int i1 = atomicAdd(&g_count[e1], 1);
        g_list[e1 * T_TOK + i1] = warp;
        g_wt  [e1 * T_TOK + i1] = w1;

        int i2 = atomicAdd(&g_count[e2], 1);
        g_list[e2 * T_TOK + i2] = warp;
        g_wt  [e2 * T_TOK + i2] = w2;
    }
}

// ---------------- tile table (parallel fill) ------------------------------
__global__ void k_build() {
    __shared__ int s_start[NEXP + 1];
    if (threadIdx.x == 0) {
        int b = 0, t = 0;
        for (int e = 0; e < NEXP; e++) {
            g_base[e]  = b;
            s_start[e] = t;
            int c = g_count[e];
            t += (c + BM - 1) / BM;
            b += c;
        }
        s_start[NEXP] = t;
        g_numTiles = t;
    }
    __syncthreads();
    int t = threadIdx.x;
    if (t < s_start[NEXP]) {
        int e = 0;
        while (t >= s_start[e + 1]) e++;
        g_tileE[t]   = e;
        g_tileRow[t] = (t - s_start[e]) * BM;
    }
}

// ---------------- weight convert: fp32 -> fp16, interleave gate/up --------
__global__ void k_splitw(const float* __restrict__ wg, const float* __restrict__ wu,
                         const float* __restrict__ wd) {
    const size_t WG = (size_t)NEXP * IDIM * HDIM;
    const size_t WD = (size_t)NEXP * HDIM * IDIM;
    size_t idx4 = (size_t)blockIdx.x * blockDim.x + threadIdx.x;
    size_t f = idx4 * 4;
    if (f < WG) {                       // gate -> row 2i
        size_t e = f / ((size_t)IDIM * HDIM);
        size_t r = f % ((size_t)IDIM * HDIM);
        size_t i = r / HDIM, k = r % HDIM;
        float4 v = *(const float4*)(wg + f);
        h_store4(v, g_w1h + ((size_t)e * N2I + 2 * i) * HDIM + k);
    } else if (f < 2 * WG) {            // up -> row 2i+1
        size_t f2 = f - WG;
        size_t e = f2 / ((size_t)IDIM * HDIM);
        size_t r = f2 % ((size_t)IDIM * HDIM);
        size_t i = r / HDIM, k = r % HDIM;
        float4 v = *(const float4*)(wu + f2);
        h_store4(v, g_w1h + ((size_t)e * N2I + 2 * i + 1) * HDIM + k);
    } else if (f < 2 * WG + WD) {       // down, linear
        size_t f2 = f - 2 * WG;
        float4 v = *(const float4*)(wd + f2);
        h_store4(v, g_wdh + f2);
    }
}

// ---------------- gather: fp32 rows -> fp16, sorted order -----------------
__global__ void k_gather(const float* __restrict__ x) {
    int p = blockIdx.x;
    int e = 0;
#pragma unroll
    for (int i = 0; i < NEXP; i++)
        if (p >= g_base[i] && p < g_base[i] + g_count[i]) e = i;
    int r   = p - g_base[e];
    int tok = g_list[e * T_TOK + r];
    const float* src = x + (size_t)tok * HDIM;
    __half* dst = g_xh + (size_t)p * HDIM;
    for (int c = threadIdx.x * 4; c < HDIM; c += blockDim.x * 4) {
        float4 v = *(const float4*)(src + c);
        h_store4(v, dst + c);
    }
}

// ---------------- persistent fused MoE GEMM -------------------------------
// Ticket queue: items [0, NT*22)  = G1 tiles (m-major): silu(gate)*up -> g_hh
//               items [NT*22, +NT*8) = G2 tiles: scaled atomicAdd -> out
// G2 tile for m waits on g_done[m]==22 (released by G1 tiles of same m).
__global__ void __launch_bounds__(256, 2) k_moe(float* __restrict__ out) {
    extern __shared__ char smem[];
    __shared__ int s_item;
    uint32_t sb = smem_u32(smem);
    int tid  = threadIdx.x;
    int lane = tid & 31, wid = tid >> 5;
    int wm0 = (wid >> 1) * 32;
    int wn0 = (wid & 1) * 64;
    int lr = lane & 7, lt = lane >> 3;
    int rowoff  = lr + (lt & 1) * 8;
    int bytesel = (lt >> 1) * 16;

    for (;;) {
        if (tid == 0) s_item = atomicAdd(&g_ticket, 1);
        __syncthreads();
        int item = s_item;
        int NT = g_numTiles;
        if (item >= NT * (NT1C + NT2C)) break;

        bool G2;
        int m, n0;
        if (item < NT * NT1C) { G2 = false; m = item / NT1C; n0 = (item % NT1C) * BN; }
        else { int j = item - NT * NT1C; G2 = true; m = j / NT2C; n0 = (j % NT2C) * BN; }

        int e = g_tileE[m], row0 = g_tileRow[m];
        int cnt = g_count[e], base = g_base[e];
        int mrem = cnt - row0;
        int KD = G2 ? IDIM : HDIM;

        const __half* aH = (G2 ? g_hh : g_xh) + (size_t)(base + row0) * KD;
        const __half* bH = G2 ? (g_wdh + ((size_t)e * HDIM + n0) * IDIM)
                              : (g_w1h + ((size_t)e * N2I + n0) * HDIM);

        if (G2) {                       // acquire: all 22 G1 tiles of m done
            if (tid == 0) {
                while (atomicAdd(&g_done[m], 0) < NT1C) __nanosleep(200);
                __threadfence();
            }
            __syncthreads();
        }

        auto load_stage = [&](int buf, int k0) {
            uint32_t s0 = sb + buf * STAGEB;
#pragma unroll
            for (int i = 0; i < 4; i++) {
                int q = tid + i * 256;
                int row = q >> 3, c = q & 7;
                uint32_t so = row * ROWB + c * 16;
                size_t go = (size_t)row * KD + k0 + c * 8;
                bool v = row < mrem;
                cp16(s0 + so, aH + go, v);            // A region at offset 0
                cp16(s0 + REG + so, bH + go, true);   // B region at offset REG
            }
            asm volatile("cp.async.commit_group;" ::: "memory");
        };

        float acc[2][8][4];
#pragma unroll
        for (int a = 0; a < 2; a++)
#pragma unroll
            for (int b = 0; b < 8; b++)
#pragma unroll
                for (int c = 0; c < 4; c++) acc[a][b][c] = 0.f;

        const int STAGES = KD / BKH;    // 16 or 22
        load_stage(0, 0);
        load_stage(1, BKH);
        int cb = 0, nb = 2;
        for (int s = 0; s < STAGES; s++) {
            asm volatile("cp.async.wait_group 1;" ::: "memory");
            __syncthreads();
            if (s + 2 < STAGES) load_stage(nb, (s + 2) * BKH);
            else asm volatile("cp.async.commit_group;" ::: "memory");

            uint32_t s0 = sb + cb * STAGEB;
#pragma unroll
            for (int ks = 0; ks < 4; ks++) {
                uint32_t kb = ks * 32 + bytesel;
                uint32_t ah[2][4];
#pragma unroll
                for (int mt = 0; mt < 2; mt++)
                    ldsm4(ah[mt], s0 + (wm0 + mt * 16 + rowoff) * ROWB + kb);
#pragma unroll
                for (int ng = 0; ng < 4; ng++) {
                    uint32_t rb = REG + (wn0 + ng * 16 + rowoff) * ROWB + kb;
                    uint32_t bh[4];
                    ldsm4(bh, s0 + rb);
#pragma unroll
                    for (int mt = 0; mt < 2; mt++) {
                        float* c0 = acc[mt][ng * 2];
                        float* c1 = acc[mt][ng * 2 + 1];
                        mma16816(c0, ah[mt], bh[0], bh[2]);
                        mma16816(c1, ah[mt], bh[1], bh[3]);
                    }
                }
            }
            cb = (cb == 2) ? 0 : cb + 1;
            nb = (nb == 2) ? 0 : nb + 1;
        }

        // ---------------- epilogue ----------------
        if (G2) {
            int gcol = n0 + wn0 + (lane & 3) * 2;
#pragma unroll
            for (int mt = 0; mt < 2; mt++) {
#pragma unroll
                for (int half = 0; half < 2; half++) {
                    int rloc = wm0 + mt * 16 + (lane >> 2) + half * 8;
                    if (rloc >= mrem) continue;
                    int gr = row0 + rloc;
                    float wscale = g_wt[e * T_TOK + gr];
                    int   tok    = g_list[e * T_TOK + gr];
                    float* outp = out + (size_t)tok * HDIM + gcol;
#pragma unroll
                    for (int nt = 0; nt < 8; nt++) {
                        atomicAdd(outp + nt * 8 + 0, acc[mt][nt][half * 2 + 0] * wscale);
                        atomicAdd(outp + nt * 8 + 1, acc[mt][nt][half * 2 + 1] * wscale);
                    }
                }
            }
        } else {
            // interleaved cols: even=gate_i, odd=up_i ; pair index in I-space
            int pairBase = (n0 >> 1) + (wn0 >> 1) + (lane & 3);
#pragma unroll
            for (int mt = 0; mt < 2; mt++) {
#pragma unroll
                for (int half = 0; half < 2; half++) {
                    int rloc = wm0 + mt * 16 + (lane >> 2) + half * 8;
                    if (rloc >= mrem) continue;
                    __half* dst = g_hh + (size_t)(base + row0 + rloc) * IDIM + pairBase;
#pragma unroll
                    for (int nt = 0; nt < 8; nt++) {
                        float g = acc[mt][nt][half * 2 + 0];
                        float u = acc[mt][nt][half * 2 + 1];
                        float h = g / (1.f + expf(-g)) * u;
                        dst[nt * 4] = __float2half_rn(h);
                    }
                }
            }
            __threadfence();            // release g_hh writes
            __syncthreads();            // all threads' stores done before count
            if (tid == 0) atomicAdd(&g_done[m], 1);
        }

        // drain cp.async + reuse smem safely next iteration
        asm volatile("cp.async.wait_group 0;" ::: "memory");
        __syncthreads();
    }
}

// ---------------- launch --------------------------------------------------
extern "C" void kernel_launch(void* const* d_in, const int* in_sizes, int n_in,
                              void* d_out, int out_size) {
    const float* x  = (const float*)d_in[0];
    const float* rw = (const float*)d_in[1];
    const float* wg = (const float*)d_in[2];
    const float* wu = (const float*)d_in[3];
    const float* wd = (const float*)d_in[4];
    float* out = (float*)d_out;

    cudaFuncSetAttribute(k_moe, cudaFuncAttributeMaxDynamicSharedMemorySize, SMEM_TOTAL);

    k_zero<<<(T_TOK * HDIM / 4 + 255) / 256, 256>>>(out);
    k_router<<<T_TOK / 8, 256>>>(x, rw);
    k_build<<<1, 128>>>();

    const size_t WG = (size_t)NEXP * IDIM * HDIM;
    const size_t WD = (size_t)NEXP * HDIM * IDIM;
    unsigned splitBlocks = (unsigned)(((2 * WG + WD) / 4 + 255) / 256);
    k_splitw<<<splitBlocks, 256>>>(wg, wu, wd);

    k_gather<<<NPAIR, 128>>>(x);

    k_moe<<<PERSIST_CTAS, 256, SMEM_TOTAL>>>(out);
}

// round 17
// speedup vs baseline: 1.0821x; 1.0821x over previous
#include <cuda_runtime.h>
#include <cuda_fp16.h>
#include <math.h>
#include <stdint.h>

#define T_TOK 4096
#define HDIM  1024
#define IDIM  1408
#define NEXP  8
#define N2I   (2 * IDIM)           // 2816 (interleaved gate/up rows)
#define BM 128
#define BN 128
#define BKH 64                     // K halves per stage (128B rows)
#define MAXT 72

// smem: rows 128B data + 16B pad = 144B (ldmatrix stride 36 words -> conflict-free)
#define ROWB 144
#define REG  (128 * ROWB)          // 18432 B per operand region
#define STAGEB (2 * REG)           // A + B = 36864
#define SMEM_TOTAL (3 * STAGEB)    // 110592 (triple-buffered) -> 2 CTAs/SM

// ---------------- scratch (static device globals; no allocations) ----------
__device__ int   g_count[NEXP];
__device__ int   g_list [NEXP * T_TOK];
__device__ float g_wt   [NEXP * T_TOK];
__device__ int   g_tileE[MAXT];
__device__ int   g_tileRow[MAXT];
__device__ int   g_numTiles;

// expert-strided layouts: expert e's rows live at [e*T_TOK + i]
__device__ __half g_xh [(size_t)NEXP * T_TOK * HDIM];
__device__ __half g_w1h[(size_t)NEXP * N2I * HDIM];   // interleaved: row 2i=gate_i, 2i+1=up_i
__device__ __half g_wdh[(size_t)NEXP * HDIM * IDIM];
__device__ __half g_hh [(size_t)NEXP * T_TOK * IDIM];

// ---------------- helpers -------------------------------------------------
__device__ __forceinline__ uint32_t smem_u32(const void* p) {
    uint32_t a;
    asm("{ .reg .u64 t; cvta.to.shared.u64 t, %1; cvt.u32.u64 %0, t; }" : "=r"(a) : "l"(p));
    return a;
}
__device__ __forceinline__ void cp16(uint32_t s, const void* g, bool v) {
    int sz = v ? 16 : 0;
    asm volatile("cp.async.cg.shared.global [%0], [%1], 16, %2;" :: "r"(s), "l"(g), "r"(sz) : "memory");
}
__device__ __forceinline__ void ldsm4(uint32_t* r, uint32_t addr) {
    asm volatile("ldmatrix.sync.aligned.m8n8.x4.shared.b16 {%0,%1,%2,%3}, [%4];"
                 : "=r"(r[0]), "=r"(r[1]), "=r"(r[2]), "=r"(r[3]) : "r"(addr));
}
__device__ __forceinline__ void mma16816(float* c, const uint32_t* a, uint32_t b0, uint32_t b1) {
    asm volatile("mma.sync.aligned.m16n8k16.row.col.f32.f16.f16.f32 "
                 "{%0,%1,%2,%3}, {%4,%5,%6,%7}, {%8,%9}, {%0,%1,%2,%3};"
                 : "+f"(c[0]), "+f"(c[1]), "+f"(c[2]), "+f"(c[3])
                 : "r"(a[0]), "r"(a[1]), "r"(a[2]), "r"(a[3]), "r"(b0), "r"(b1));
}
__device__ __forceinline__ void h_store4(float4 v, __half* hp) {
    ((__half2*)hp)[0] = __halves2half2(__float2half_rn(v.x), __float2half_rn(v.y));
    ((__half2*)hp)[1] = __halves2half2(__float2half_rn(v.z), __float2half_rn(v.w));
}

// ---------------- zero output + control state -----------------------------
__global__ void k_zero(float* __restrict__ out) {
    size_t idx = (size_t)blockIdx.x * blockDim.x + threadIdx.x;
    if (idx < (size_t)T_TOK * HDIM / 4)
        *(float4*)(out + idx * 4) = make_float4(0.f, 0.f, 0.f, 0.f);
    if (blockIdx.x == 0 && threadIdx.x < NEXP) g_count[threadIdx.x] = 0;
}

// ---------------- router + scatter: one warp per token --------------------
// Computes top-2 and writes the fp16 row straight into expert-strided g_xh.
__global__ void k_router(const float* __restrict__ x, const float* __restrict__ rw) {
    int warp = (blockIdx.x * blockDim.x + threadIdx.x) >> 5;
    int lane = threadIdx.x & 31;
    if (warp >= T_TOK) return;
    const float* xr = x + (size_t)warp * HDIM;

    float xv[32];
#pragma unroll
    for (int j = 0; j < 32; j++) xv[j] = xr[lane + j * 32];

    float logits[NEXP];
#pragma unroll
    for (int e = 0; e < NEXP; e++) {
        const float* wr = rw + (size_t)e * HDIM;
        float acc = 0.f;
#pragma unroll
        for (int j = 0; j < 32; j++) acc += xv[j] * wr[lane + j * 32];
#pragma unroll
        for (int s = 16; s > 0; s >>= 1) acc += __shfl_xor_sync(0xffffffffu, acc, s);
        logits[e] = acc;
    }

    int e1 = 0, e2 = 0, i1 = 0, i2 = 0;
    if (lane == 0) {
        e1 = 0;
#pragma unroll
        for (int e = 1; e < NEXP; e++) if (logits[e] > logits[e1]) e1 = e;
        e2 = (e1 == 0) ? 1 : 0;
#pragma unroll
        for (int e = 0; e < NEXP; e++)
            if (e != e1 && logits[e] > logits[e2]) e2 = e;
        float t  = expf(logits[e2] - logits[e1]);
        float w1 = 1.f / (1.f + t);
        float w2 = t   / (1.f + t);

        i1 = atomicAdd(&g_count[e1], 1);
        g_list[e1 * T_TOK + i1] = warp;
        g_wt  [e1 * T_TOK + i1] = w1;

        i2 = atomicAdd(&g_count[e2], 1);
        g_list[e2 * T_TOK + i2] = warp;
        g_wt  [e2 * T_TOK + i2] = w2;
    }
    e1 = __shfl_sync(0xffffffffu, e1, 0);
    e2 = __shfl_sync(0xffffffffu, e2, 0);
    i1 = __shfl_sync(0xffffffffu, i1, 0);
    i2 = __shfl_sync(0xffffffffu, i2, 0);

    __half hv[32];
#pragma unroll
    for (int j = 0; j < 32; j++) hv[j] = __float2half_rn(xv[j]);

    __half* d1 = g_xh + ((size_t)e1 * T_TOK + i1) * HDIM;
    __half* d2 = g_xh + ((size_t)e2 * T_TOK + i2) * HDIM;
#pragma unroll
    for (int j = 0; j < 32; j++) {
        d1[lane + j * 32] = hv[j];
        d2[lane + j * 32] = hv[j];
    }
}

// ---------------- tile table (parallel fill) ------------------------------
__global__ void k_build() {
    __shared__ int s_start[NEXP + 1];
    if (threadIdx.x == 0) {
        int t = 0;
        for (int e = 0; e < NEXP; e++) {
            s_start[e] = t;
            t += (g_count[e] + BM - 1) / BM;
        }
        s_start[NEXP] = t;
        g_numTiles = t;
    }
    __syncthreads();
    int t = threadIdx.x;
    if (t < s_start[NEXP]) {
        int e = 0;
        while (t >= s_start[e + 1]) e++;
        g_tileE[t]   = e;
        g_tileRow[t] = (t - s_start[e]) * BM;
    }
}

// ---------------- weight convert: fp32 -> fp16, interleave gate/up --------
__global__ void k_splitw(const float* __restrict__ wg, const float* __restrict__ wu,
                         const float* __restrict__ wd) {
    const size_t WG = (size_t)NEXP * IDIM * HDIM;
    const size_t WD = (size_t)NEXP * HDIM * IDIM;
    size_t idx4 = (size_t)blockIdx.x * blockDim.x + threadIdx.x;
    size_t f = idx4 * 4;
    if (f < WG) {                       // gate -> row 2i
        size_t e = f / ((size_t)IDIM * HDIM);
        size_t r = f % ((size_t)IDIM * HDIM);
        size_t i = r / HDIM, k = r % HDIM;
        float4 v = *(const float4*)(wg + f);
        h_store4(v, g_w1h + ((size_t)e * N2I + 2 * i) * HDIM + k);
    } else if (f < 2 * WG) {            // up -> row 2i+1
        size_t f2 = f - WG;
        size_t e = f2 / ((size_t)IDIM * HDIM);
        size_t r = f2 % ((size_t)IDIM * HDIM);
        size_t i = r / HDIM, k = r % HDIM;
        float4 v = *(const float4*)(wu + f2);
        h_store4(v, g_w1h + ((size_t)e * N2I + 2 * i + 1) * HDIM + k);
    } else if (f < 2 * WG + WD) {       // down, linear
        size_t f2 = f - 2 * WG;
        float4 v = *(const float4*)(wd + f2);
        h_store4(v, g_wdh + f2);
    }
}

// ---------------- fp16 HMMA GEMM, 3-stage pipeline ------------------------
// G1: C = Ah @ B1^T, fused silu(gate)*up -> g_hh (interleaved cols)
// G2: C = Ah @ Bd^T, scaled atomic accumulate -> out
template <int KD, bool G2>
__global__ void __launch_bounds__(256, 2) k_gemm(float* __restrict__ out) {
    constexpr uint32_t O_AH = 0, O_BH = REG;

    int tileIdx = blockIdx.y;
    if (tileIdx >= g_numTiles) return;
    extern __shared__ char smem[];
    uint32_t sb = smem_u32(smem);
    int tid  = threadIdx.x;
    int lane = tid & 31, wid = tid >> 5;
    int wm0 = (wid >> 1) * 32;
    int wn0 = (wid & 1) * 64;

    int e = g_tileE[tileIdx], row0 = g_tileRow[tileIdx];
    int cnt = g_count[e];
    int n0 = blockIdx.x * BN;
    int mrem = cnt - row0;

    const __half* aH = (G2 ? g_hh : g_xh) + ((size_t)e * T_TOK + row0) * KD;
    const __half* bH = G2 ? (g_wdh + ((size_t)e * HDIM + n0) * IDIM)
                          : (g_w1h + ((size_t)e * N2I + n0) * HDIM);

    auto load_stage = [&](int buf, int k0) {
        uint32_t s0 = sb + buf * STAGEB;
#pragma unroll
        for (int i = 0; i < 4; i++) {
            int q = tid + i * 256;
            int row = q >> 3, c = q & 7;
            uint32_t so = row * ROWB + c * 16;
            size_t go = (size_t)row * KD + k0 + c * 8;
            bool v = row < mrem;
            cp16(s0 + O_AH + so, aH + go, v);
            cp16(s0 + O_BH + so, bH + go, true);
        }
        asm volatile("cp.async.commit_group;" ::: "memory");
    };

    float acc[2][8][4];
#pragma unroll
    for (int a = 0; a < 2; a++)
#pragma unroll
        for (int b = 0; b < 8; b++)
#pragma unroll
            for (int c = 0; c < 4; c++) acc[a][b][c] = 0.f;

    int lr = lane & 7, lt = lane >> 3;
    int rowoff  = lr + (lt & 1) * 8;
    int bytesel = (lt >> 1) * 16;

    const int STAGES = KD / BKH;
    load_stage(0, 0);
    load_stage(1, BKH);
    int cb = 0, nb = 2;                 // compute buf, next load buf
    for (int s = 0; s < STAGES; s++) {
        asm volatile("cp.async.wait_group 1;" ::: "memory");
        __syncthreads();
        if (s + 2 < STAGES) load_stage(nb, (s + 2) * BKH);
        else asm volatile("cp.async.commit_group;" ::: "memory");

        uint32_t s0 = sb + cb * STAGEB;
#pragma unroll
        for (int ks = 0; ks < 4; ks++) {
            uint32_t kb = ks * 32 + bytesel;
            uint32_t ah[2][4];
#pragma unroll
            for (int mt = 0; mt < 2; mt++)
                ldsm4(ah[mt], s0 + O_AH + (wm0 + mt * 16 + rowoff) * ROWB + kb);
#pragma unroll
            for (int ng = 0; ng < 4; ng++) {
                uint32_t rb = (wn0 + ng * 16 + rowoff) * ROWB + kb;
                uint32_t bh[4];
                ldsm4(bh, s0 + O_BH + rb);
#pragma unroll
                for (int mt = 0; mt < 2; mt++) {
                    float* c0 = acc[mt][ng * 2];
                    float* c1 = acc[mt][ng * 2 + 1];
                    mma16816(c0, ah[mt], bh[0], bh[2]);
                    mma16816(c1, ah[mt], bh[1], bh[3]);
                }
            }
        }
        cb = (cb == 2) ? 0 : cb + 1;
        nb = (nb == 2) ? 0 : nb + 1;
    }

    // ---------------- epilogue ----------------
    if (G2) {
        int gcol = n0 + wn0 + (lane & 3) * 2;
#pragma unroll
        for (int mt = 0; mt < 2; mt++) {
#pragma unroll
            for (int half = 0; half < 2; half++) {
                int rloc = wm0 + mt * 16 + (lane >> 2) + half * 8;
                if (rloc >= mrem) continue;
                int gr = row0 + rloc;
                float wscale = g_wt[e * T_TOK + gr];
                int   tok    = g_list[e * T_TOK + gr];
                float* outp = out + (size_t)tok * HDIM + gcol;
#pragma unroll
                for (int nt = 0; nt < 8; nt++) {
                    atomicAdd(outp + nt * 8 + 0, acc[mt][nt][half * 2 + 0] * wscale);
                    atomicAdd(outp + nt * 8 + 1, acc[mt][nt][half * 2 + 1] * wscale);
                }
            }
        }
    } else {
        // interleaved cols: even=gate_i, odd=up_i ; pair index in I-space
        int pairBase = (n0 >> 1) + (wn0 >> 1) + (lane & 3);
#pragma unroll
        for (int mt = 0; mt < 2; mt++) {
#pragma unroll
            for (int half = 0; half < 2; half++) {
                int rloc = wm0 + mt * 16 + (lane >> 2) + half * 8;
                if (rloc >= mrem) continue;
                __half* dst = g_hh + ((size_t)e * T_TOK + row0 + rloc) * IDIM + pairBase;
#pragma unroll
                for (int nt = 0; nt < 8; nt++) {
                    float g = acc[mt][nt][half * 2 + 0];
                    float u = acc[mt][nt][half * 2 + 1];
                    float h = g / (1.f + expf(-g)) * u;
                    dst[nt * 4] = __float2half_rn(h);
                }
            }
        }
    }
}

// ---------------- launch --------------------------------------------------
extern "C" void kernel_launch(void* const* d_in, const int* in_sizes, int n_in,
                              void* d_out, int out_size) {
    const float* x  = (const float*)d_in[0];
    const float* rw = (const float*)d_in[1];
    const float* wg = (const float*)d_in[2];
    const float* wu = (const float*)d_in[3];
    const float* wd = (const float*)d_in[4];
    float* out = (float*)d_out;

    cudaFuncSetAttribute(k_gemm<HDIM, false>,
                         cudaFuncAttributeMaxDynamicSharedMemorySize, SMEM_TOTAL);
    cudaFuncSetAttribute(k_gemm<IDIM, true>,
                         cudaFuncAttributeMaxDynamicSharedMemorySize, SMEM_TOTAL);

    k_zero<<<(T_TOK * HDIM / 4 + 255) / 256, 256>>>(out);
    k_router<<<T_TOK / 8, 256>>>(x, rw);
    k_build<<<1, 128>>>();

    const size_t WG = (size_t)NEXP * IDIM * HDIM;
    const size_t WD = (size_t)NEXP * HDIM * IDIM;
    unsigned splitBlocks = (unsigned)(((2 * WG + WD) / 4 + 255) / 256);
    k_splitw<<<splitBlocks, 256>>>(wg, wu, wd);

    dim3 g1(N2I / BN, MAXT);   // (22, 72)
    k_gemm<HDIM, false><<<g1, 256, SMEM_TOTAL>>>(nullptr);

    dim3 g2(HDIM / BN, MAXT);  // (8, 72)
    k_gemm<IDIM, true><<<g2, 256, SMEM_TOTAL>>>(out);
}